// round 6
// baseline (speedup 1.0000x reference)
#include <cuda_runtime.h>
#include <cuda_bf16.h>
#include <cstdint>
#include <math.h>

// ---------------- problem constants ----------------
#define N_IMG 16
#define CI    64
#define HW    224
#define PLANE (HW*HW)       // 50176
#define CO    128
#define OH    222
#define OW    222
#define KPOS  9
#define KTOT  (CI*KPOS)     // 576

// ---------------- config ----------------
#define THREADS 512
#define NWARPS  16
#define NSM 148
#define PAIRS_PER_STRIP (OH/2)                 // 111
#define PAIRS_TOTAL (N_IMG*2*PAIRS_PER_STRIP)  // 3552 = 148*24
#define PAIRS_PER_CTA (PAIRS_TOTAL/NSM)        // 24

// W smem: [co 128][k 576 pad 584] bf16, row stride 1168B (292 words % 32 = 4: conflict-free)
#define WK_PAD   584
#define W_ROWB   (WK_PAD*2)              // 1168
#define OFF_W    0
#define W_BYTES  (CO*W_ROWB)             // 149504

// S smem: ring of 4 planes, plane = [col 132][ci 64 pad 72] bf16
#define S_CIPAD  72
#define S_COLB   (S_CIPAD*2)             // 144
#define S_PLANEB (132*S_COLB)            // 19008
#define OFF_S    W_BYTES                 // 149504
#define S_BYTES  (4*S_PLANEB)            // 76032

#define OFF_BIAS (OFF_S + S_BYTES)       // 225536 (128 floats)
#define OFF_MIN  (OFF_BIAS + 512)        // 226048 (512 floats: [g][px][wn])
#define SMEM_TOTAL (OFF_MIN + 2048)      // 228096

// ---------------- PTX helpers ----------------
__device__ __forceinline__ uint32_t smem_u32(const void* p) {
    uint32_t a;
    asm("{ .reg .u64 t; cvta.to.shared.u64 t, %1; cvt.u32.u64 %0, t; }" : "=r"(a) : "l"(p));
    return a;
}

#define LDSM_X4(r, addr) \
    asm volatile("ldmatrix.sync.aligned.m8n8.x4.shared.b16 {%0,%1,%2,%3}, [%4];" \
        : "=r"((r)[0]), "=r"((r)[1]), "=r"((r)[2]), "=r"((r)[3]) : "r"(addr))

__device__ __forceinline__ void mma_bf16(float* d, const uint32_t* a, const uint32_t* b) {
    asm volatile("mma.sync.aligned.m16n8k16.row.col.f32.bf16.bf16.f32 "
        "{%0,%1,%2,%3}, {%4,%5,%6,%7}, {%8,%9}, {%0,%1,%2,%3};"
        : "+f"(d[0]), "+f"(d[1]), "+f"(d[2]), "+f"(d[3])
        : "r"(a[0]), "r"(a[1]), "r"(a[2]), "r"(a[3]), "r"(b[0]), "r"(b[1]));
}

__device__ __forceinline__ uint32_t pack_bf16(float lo, float hi) {
    __nv_bfloat162 t = __floats2bfloat162_rn(lo, hi);
    return *(uint32_t*)&t;
}

// ---------------- staging: one plane = input row r_in, 64 ci, 132 cols ----------------
// 40 tasks: oct(8) x colgroup(5); 16 warps -> tasks tk = wid + 16j (j<3 guarded).
__device__ __forceinline__ void stage_plane_direct(
    const float* __restrict__ x, int n, int r_in, int ow0,
    uint32_t sb, int wid, int lane)
{
    const uint32_t slotB = sb + OFF_S + (uint32_t)(r_in & 3) * S_PLANEB;
    #pragma unroll
    for (int j = 0; j < 3; ++j) {
        int tk = wid + NWARPS * j;
        if (tk >= 40) break;
        int oct = tk / 5;
        int cg  = tk - oct * 5;
        int col = cg * 32 + lane;
        bool stv = (col < 132);
        bool ldv = stv && (ow0 + col < HW);
        const float* gp = x + ((size_t)n * CI + oct * 8) * PLANE
                            + (size_t)r_in * HW + (ow0 + col);
        float v[8];
        #pragma unroll
        for (int q = 0; q < 8; ++q) v[q] = ldv ? gp[(size_t)q * PLANE] : 0.0f;
        if (stv) {
            uint32_t pk0 = pack_bf16(v[0], v[1]);
            uint32_t pk1 = pack_bf16(v[2], v[3]);
            uint32_t pk2 = pack_bf16(v[4], v[5]);
            uint32_t pk3 = pack_bf16(v[6], v[7]);
            uint32_t sa = slotB + (uint32_t)col * S_COLB + (uint32_t)oct * 16;
            asm volatile("st.shared.v4.b32 [%0], {%1,%2,%3,%4};"
                         :: "r"(sa), "r"(pk0), "r"(pk1), "r"(pk2), "r"(pk3));
        }
    }
}

// ---------------- kernel ----------------
__global__ __launch_bounds__(THREADS, 1)
void conv_min_tanh_mma4(const float* __restrict__ x,
                        const float* __restrict__ wgt,
                        const float* __restrict__ bias,
                        float* __restrict__ out)
{
    extern __shared__ char smem[];
    const uint32_t sb = smem_u32(smem);
    const int tid  = threadIdx.x;
    const int lane = tid & 31;
    const int wid  = tid >> 5;
    const int g    = wid >> 3;        // row group 0/1
    const int wid2 = wid & 7;
    const int wm   = wid2 & 3;        // pixel group (32 px)
    const int wn   = wid2 >> 2;       // co half (64 co)
    float* bias_sm = (float*)(smem + OFF_BIAS);
    float* min_sm  = (float*)(smem + OFF_MIN);

    // ---- stage weights once: W[co][k], k = kp*64 + ci, bf16 ----
    for (int i = tid; i < CO * KTOT; i += THREADS) {
        int co  = i / KTOT;
        int rem = i - co * KTOT;        // ci*9 + kp
        int ci  = rem / KPOS;
        int kp  = rem - ci * KPOS;
        int k   = kp * 64 + ci;
        *(__nv_bfloat16*)(smem + OFF_W + co * W_ROWB + k * 2) = __float2bfloat16(wgt[i]);
    }
    if (tid < CO) bias_sm[tid] = bias[tid];
    __syncthreads();

    // per-thread bias regs: co = wn*64 + nt*8 + 2*(lane&3) + {0,1}, nt in [0,8)
    float blo[8], bhi[8];
    #pragma unroll
    for (int nt = 0; nt < 8; ++nt) {
        int c = wn * 64 + nt * 8 + 2 * (lane & 3);
        blo[nt] = bias_sm[c];
        bhi[nt] = bias_sm[c + 1];
    }

    // ldmatrix lane address components
    const uint32_t aCol = (uint32_t)(wm * 32 + (lane & 15)) * S_COLB
                        + (uint32_t)(lane >> 4) * 16;
    const uint32_t bBase = sb + OFF_W
        + (uint32_t)(wn * 64 + (lane & 7) + ((lane >> 4) & 1) * 8) * W_ROWB
        + (uint32_t)((lane >> 3) & 1) * 16;

    int prev_strip = -1;

    for (int iter = 0; iter < PAIRS_PER_CTA; ++iter) {
        const int P     = blockIdx.x * PAIRS_PER_CTA + iter;
        const int strip = P / PAIRS_PER_STRIP;           // 0..31 : (n, half)
        const int pr    = P - strip * PAIRS_PER_STRIP;   // 0..110
        const int oh    = pr * 2;                        // rows oh, oh+1
        const int n     = strip >> 1;
        const int ow0   = (strip & 1) ? (OW - 128) : 0;

        // ---- strip entry: stage 4 planes fresh ----
        if (strip != prev_strip) {
            stage_plane_direct(x, n, oh + 0, ow0, sb, wid, lane);
            stage_plane_direct(x, n, oh + 1, ow0, sb, wid, lane);
            stage_plane_direct(x, n, oh + 2, ow0, sb, wid, lane);
            stage_plane_direct(x, n, oh + 3, ow0, sb, wid, lane);
            __syncthreads();
            prev_strip = strip;
        }
        // invariant: planes oh..oh+3 in ring, visible

        const bool next_same = (iter + 1 < PAIRS_PER_CTA) && (pr + 1 < PAIRS_PER_STRIP);

        // ---- prefetch next pair's planes (rows oh+4, oh+5): 80 tasks, 5/warp,
        //      packed to bf16 immediately (20 u32 regs) ----
        uint32_t pfp[5][4];
        if (next_same) {
            #pragma unroll
            for (int j = 0; j < 5; ++j) {
                int tk    = wid + NWARPS * j;     // 0..79
                int plane = tk / 40;              // 0 -> oh+4, 1 -> oh+5
                int r     = tk - plane * 40;
                int oct   = r / 5;
                int cg    = r - oct * 5;
                int col   = cg * 32 + lane;
                bool ldv  = (col < 132) && (ow0 + col < HW);
                const float* gp = x + ((size_t)n * CI + oct * 8) * PLANE
                                    + (size_t)(oh + 4 + plane) * HW + (ow0 + col);
                float v[8];
                #pragma unroll
                for (int q = 0; q < 8; ++q) v[q] = ldv ? gp[(size_t)q * PLANE] : 0.0f;
                pfp[j][0] = pack_bf16(v[0], v[1]);
                pfp[j][1] = pack_bf16(v[2], v[3]);
                pfp[j][2] = pack_bf16(v[4], v[5]);
                pfp[j][3] = pack_bf16(v[6], v[7]);
            }
        }

        // ---- MMA: row oh+g, warp tile 32px x 64co; K = 9 kpos x 4 ksteps ----
        float acc[2][8][4];
        #pragma unroll
        for (int mi = 0; mi < 2; ++mi)
            #pragma unroll
            for (int nt = 0; nt < 8; ++nt)
                #pragma unroll
                for (int q = 0; q < 4; ++q) acc[mi][nt][q] = 0.0f;

        #pragma unroll 1
        for (int kp = 0; kp < KPOS; ++kp) {
            const int kh = kp / 3, kw = kp - 3 * (kp / 3);
            const uint32_t aKp = sb + OFF_S + (uint32_t)((oh + g + kh) & 3) * S_PLANEB
                               + aCol + (uint32_t)kw * S_COLB;
            const uint32_t kB  = (uint32_t)(kp * 64) * 2;
            #pragma unroll
            for (int ks = 0; ks < 4; ++ks) {
                uint32_t a0[4], a1[4];
                LDSM_X4(a0, aKp + ks * 32);
                LDSM_X4(a1, aKp + ks * 32 + 16 * S_COLB);
                uint32_t bf[4][4];
                #pragma unroll
                for (int ntp = 0; ntp < 4; ++ntp)
                    LDSM_X4(bf[ntp], bBase + (uint32_t)ntp * 16 * W_ROWB + kB + ks * 32);
                #pragma unroll
                for (int ntp = 0; ntp < 4; ++ntp) {
                    mma_bf16(acc[0][2 * ntp + 0], a0, &bf[ntp][0]);
                    mma_bf16(acc[0][2 * ntp + 1], a0, &bf[ntp][2]);
                    mma_bf16(acc[1][2 * ntp + 0], a1, &bf[ntp][0]);
                    mma_bf16(acc[1][2 * ntp + 1], a1, &bf[ntp][2]);
                }
            }
        }

        // ---- epilogue: bias + min over this warp's 64 co ----
        float v4[4];  // [mi*2 + h], h: 0 = row, 1 = row+8
        #pragma unroll
        for (int mi = 0; mi < 2; ++mi) {
            float r0 = INFINITY, r1 = INFINITY;
            #pragma unroll
            for (int nt = 0; nt < 8; ++nt) {
                r0 = fminf(r0, fminf(acc[mi][nt][0] + blo[nt], acc[mi][nt][1] + bhi[nt]));
                r1 = fminf(r1, fminf(acc[mi][nt][2] + blo[nt], acc[mi][nt][3] + bhi[nt]));
            }
            v4[mi * 2 + 0] = r0;
            v4[mi * 2 + 1] = r1;
        }
        #pragma unroll
        for (int j = 0; j < 4; ++j) {
            v4[j] = fminf(v4[j], __shfl_xor_sync(0xFFFFFFFFu, v4[j], 1));
            v4[j] = fminf(v4[j], __shfl_xor_sync(0xFFFFFFFFu, v4[j], 2));
        }
        if ((lane & 3) == 0) {
            int row = lane >> 2;
            #pragma unroll
            for (int mi = 0; mi < 2; ++mi) {
                int px0 = wm * 32 + mi * 16 + row;
                min_sm[g * 256 + px0 * 2 + wn]       = v4[mi * 2 + 0];
                min_sm[g * 256 + (px0 + 8) * 2 + wn] = v4[mi * 2 + 1];
            }
        }
        __syncthreads();
        if (tid < 256) {
            int gg = tid >> 7, px = tid & 127;
            float2 q = *(const float2*)(min_sm + gg * 256 + px * 2);
            float m = fminf(q.x, q.y);
            out[((size_t)n * OH + oh + gg) * OW + ow0 + px] = tanhf(tanhf(m));
        }

        // ---- store prefetched planes into ring slots (oh+4)&3, (oh+5)&3 ----
        if (next_same) {
            #pragma unroll
            for (int j = 0; j < 5; ++j) {
                int tk    = wid + NWARPS * j;
                int plane = tk / 40;
                int r     = tk - plane * 40;
                int oct   = r / 5;
                int cg    = r - oct * 5;
                int col   = cg * 32 + lane;
                if (col < 132) {
                    uint32_t sa = sb + OFF_S
                                + (uint32_t)((oh + 4 + plane) & 3) * S_PLANEB
                                + (uint32_t)col * S_COLB + (uint32_t)oct * 16;
                    asm volatile("st.shared.v4.b32 [%0], {%1,%2,%3,%4};"
                                 :: "r"(sa), "r"(pfp[j][0]), "r"(pfp[j][1]),
                                    "r"(pfp[j][2]), "r"(pfp[j][3]));
                }
            }
        }
        __syncthreads();  // planes visible for next pair; min_sm safe for reuse
    }
}

extern "C" void kernel_launch(void* const* d_in, const int* in_sizes, int n_in,
                              void* d_out, int out_size)
{
    const float* x    = (const float*)d_in[0];
    const float* wgt  = (const float*)d_in[1];
    const float* bias = (const float*)d_in[2];
    float* out        = (float*)d_out;

    cudaFuncSetAttribute(conv_min_tanh_mma4,
                         cudaFuncAttributeMaxDynamicSharedMemorySize, SMEM_TOTAL);
    conv_min_tanh_mma4<<<NSM, THREADS, SMEM_TOTAL>>>(x, wgt, bias, out);
}

// round 7
// speedup vs baseline: 1.0811x; 1.0811x over previous
#include <cuda_runtime.h>
#include <cuda_bf16.h>
#include <cstdint>
#include <math.h>

// ---------------- problem constants ----------------
#define N_IMG 16
#define CI    64
#define HW    224
#define PLANE (HW*HW)       // 50176
#define CO    128
#define OH    222
#define OW    222
#define KPOS  9
#define KTOT  (CI*KPOS)     // 576

// ---------------- config ----------------
#define THREADS 512
#define NSM 148
#define TILES_TOTAL (N_IMG*OH*2)         // 7104 = 148*48
#define TILES_PER_CTA (TILES_TOTAL/NSM)  // 48

// W smem: [co 128][k 576 pad 584] bf16, row stride 1168B (292 words % 32 = 4: conflict-free)
#define WK_PAD   584
#define W_ROWB   (WK_PAD*2)              // 1168
#define OFF_W    0
#define W_BYTES  (CO*W_ROWB)             // 149504

// S smem: ring of 4 planes, plane = [col 132][ci 64 pad 72] bf16
#define S_CIPAD  72
#define S_COLB   (S_CIPAD*2)             // 144
#define S_PLANEB (132*S_COLB)            // 19008
#define OFF_S    W_BYTES                 // 149504
#define S_BYTES  (4*S_PLANEB)            // 76032

#define OFF_BIAS (OFF_S + S_BYTES)       // 225536 (128 floats)
#define OFF_MIN  (OFF_BIAS + 512)        // 226048 (256 floats)
#define SMEM_TOTAL (OFF_MIN + 1024)      // 227072

// named barriers
#define BAR_ALL()  asm volatile("bar.sync 1, %0;" :: "n"(THREADS) : "memory")
#define BAR_CONS() asm volatile("bar.sync 2, 256;" ::: "memory")

// ---------------- PTX helpers ----------------
__device__ __forceinline__ uint32_t smem_u32(const void* p) {
    uint32_t a;
    asm("{ .reg .u64 t; cvta.to.shared.u64 t, %1; cvt.u32.u64 %0, t; }" : "=r"(a) : "l"(p));
    return a;
}

#define LDSM_X4(r, addr) \
    asm volatile("ldmatrix.sync.aligned.m8n8.x4.shared.b16 {%0,%1,%2,%3}, [%4];" \
        : "=r"((r)[0]), "=r"((r)[1]), "=r"((r)[2]), "=r"((r)[3]) : "r"(addr))

__device__ __forceinline__ void mma_bf16(float* d, const uint32_t* a, const uint32_t* b) {
    asm volatile("mma.sync.aligned.m16n8k16.row.col.f32.bf16.bf16.f32 "
        "{%0,%1,%2,%3}, {%4,%5,%6,%7}, {%8,%9}, {%0,%1,%2,%3};"
        : "+f"(d[0]), "+f"(d[1]), "+f"(d[2]), "+f"(d[3])
        : "r"(a[0]), "r"(a[1]), "r"(a[2]), "r"(a[3]), "r"(b[0]), "r"(b[1]));
}

__device__ __forceinline__ uint32_t pack_bf16(float lo, float hi) {
    __nv_bfloat162 t = __floats2bfloat162_rn(lo, hi);
    return *(uint32_t*)&t;
}

// ---------------- one staging task: oct (8 ci), 32 cols ----------------
__device__ __forceinline__ void stage_task(
    const float* __restrict__ x, int n, int r_in, int ow0,
    int oct, int cg, int lane, uint32_t sb)
{
    int col = cg * 32 + lane;
    bool stv = (col < 132);
    bool ldv = stv && (ow0 + col < HW);
    const float* gp = x + ((size_t)n * CI + oct * 8) * PLANE
                        + (size_t)r_in * HW + (ow0 + col);
    float v[8];
    #pragma unroll
    for (int q = 0; q < 8; ++q) v[q] = ldv ? gp[(size_t)q * PLANE] : 0.0f;
    if (stv) {
        uint32_t pk0 = pack_bf16(v[0], v[1]);
        uint32_t pk1 = pack_bf16(v[2], v[3]);
        uint32_t pk2 = pack_bf16(v[4], v[5]);
        uint32_t pk3 = pack_bf16(v[6], v[7]);
        uint32_t sa = sb + OFF_S + (uint32_t)(r_in & 3) * S_PLANEB
                    + (uint32_t)col * S_COLB + (uint32_t)oct * 16;
        asm volatile("st.shared.v4.b32 [%0], {%1,%2,%3,%4};"
                     :: "r"(sa), "r"(pk0), "r"(pk1), "r"(pk2), "r"(pk3));
    }
}

// ---------------- kernel ----------------
__global__ __launch_bounds__(THREADS, 1)
void conv_min_tanh_ws(const float* __restrict__ x,
                      const float* __restrict__ wgt,
                      const float* __restrict__ bias,
                      float* __restrict__ out)
{
    extern __shared__ char smem[];
    const uint32_t sb = smem_u32(smem);
    const int tid  = threadIdx.x;
    const int lane = tid & 31;
    const int wid  = tid >> 5;
    const bool consumer = (wid < 8);
    const int wm   = wid & 3;        // consumer: pixel group (32 px)
    const int wn   = (wid >> 2) & 1; // consumer: co half (64 co)
    float* bias_sm = (float*)(smem + OFF_BIAS);
    float* min_sm  = (float*)(smem + OFF_MIN);

    // ---- stage weights once: W[co][k], k = kp*64 + ci, bf16 (all warps) ----
    for (int i = tid; i < CO * KTOT; i += THREADS) {
        int co  = i / KTOT;
        int rem = i - co * KTOT;        // ci*9 + kp
        int ci  = rem / KPOS;
        int kp  = rem - ci * KPOS;
        int k   = kp * 64 + ci;
        *(__nv_bfloat16*)(smem + OFF_W + co * W_ROWB + k * 2) = __float2bfloat16(wgt[i]);
    }
    if (tid < CO) bias_sm[tid] = bias[tid];
    __syncthreads();

    // consumer per-thread bias regs: co = wn*64 + nt*8 + 2*(lane&3) + {0,1}
    float blo[8], bhi[8];
    #pragma unroll
    for (int nt = 0; nt < 8; ++nt) {
        int c = wn * 64 + nt * 8 + 2 * (lane & 3);
        blo[nt] = bias_sm[c];
        bhi[nt] = bias_sm[c + 1];
    }

    // consumer ldmatrix lane address components
    const uint32_t aCol = (uint32_t)(wm * 32 + (lane & 15)) * S_COLB
                        + (uint32_t)(lane >> 4) * 16;
    const uint32_t bBase = sb + OFF_W
        + (uint32_t)(wn * 64 + (lane & 7) + ((lane >> 4) & 1) * 8) * W_ROWB
        + (uint32_t)((lane >> 3) & 1) * 16;

    int prev_strip = -1;

    for (int iter = 0; iter < TILES_PER_CTA; ++iter) {
        const int t     = blockIdx.x * TILES_PER_CTA + iter;
        const int strip = t / OH;              // 0..31 : (n, half)
        const int oh    = t - strip * OH;      // row within strip
        const int n     = strip >> 1;
        const int ow0   = (strip & 1) ? (OW - 128) : 0;

        // ---- strip entry: ALL warps stage planes oh..oh+2 (120 tasks) ----
        if (strip != prev_strip) {
            #pragma unroll 1
            for (int j = 0; j < 8; ++j) {
                int tk = wid + 16 * j;
                if (tk >= 120) break;
                int pl  = tk / 40;
                int r   = tk - pl * 40;
                int oct = r / 5;
                int cg  = r - oct * 5;
                stage_task(x, n, oh + pl, ow0, oct, cg, lane, sb);
            }
            BAR_ALL();
            prev_strip = strip;
        }
        // invariant: planes oh, oh+1, oh+2 staged & visible

        if (consumer) {
            // ---- MMA: warp tile 32px x 64co; K = 9 kpos x 4 ksteps ----
            float acc[2][8][4];
            #pragma unroll
            for (int mi = 0; mi < 2; ++mi)
                #pragma unroll
                for (int nt = 0; nt < 8; ++nt)
                    #pragma unroll
                    for (int q = 0; q < 4; ++q) acc[mi][nt][q] = 0.0f;

            #pragma unroll 1
            for (int kp = 0; kp < KPOS; ++kp) {
                const int kh = kp / 3, kw = kp - 3 * (kp / 3);
                const uint32_t aKp = sb + OFF_S + (uint32_t)((oh + kh) & 3) * S_PLANEB
                                   + aCol + (uint32_t)kw * S_COLB;
                const uint32_t kB  = (uint32_t)(kp * 64) * 2;
                #pragma unroll
                for (int ks = 0; ks < 4; ++ks) {
                    uint32_t a0[4], a1[4];
                    LDSM_X4(a0, aKp + ks * 32);
                    LDSM_X4(a1, aKp + ks * 32 + 16 * S_COLB);
                    uint32_t bf[4][4];
                    #pragma unroll
                    for (int ntp = 0; ntp < 4; ++ntp)
                        LDSM_X4(bf[ntp], bBase + (uint32_t)ntp * 16 * W_ROWB + kB + ks * 32);
                    #pragma unroll
                    for (int ntp = 0; ntp < 4; ++ntp) {
                        mma_bf16(acc[0][2 * ntp + 0], a0, &bf[ntp][0]);
                        mma_bf16(acc[0][2 * ntp + 1], a0, &bf[ntp][2]);
                        mma_bf16(acc[1][2 * ntp + 0], a1, &bf[ntp][0]);
                        mma_bf16(acc[1][2 * ntp + 1], a1, &bf[ntp][2]);
                    }
                }
            }

            // ---- epilogue: bias + min over this warp's 64 co ----
            float v4[4];  // [mi*2 + h]
            #pragma unroll
            for (int mi = 0; mi < 2; ++mi) {
                float r0 = INFINITY, r1 = INFINITY;
                #pragma unroll
                for (int nt = 0; nt < 8; ++nt) {
                    r0 = fminf(r0, fminf(acc[mi][nt][0] + blo[nt], acc[mi][nt][1] + bhi[nt]));
                    r1 = fminf(r1, fminf(acc[mi][nt][2] + blo[nt], acc[mi][nt][3] + bhi[nt]));
                }
                v4[mi * 2 + 0] = r0;
                v4[mi * 2 + 1] = r1;
            }
            #pragma unroll
            for (int j = 0; j < 4; ++j) {
                v4[j] = fminf(v4[j], __shfl_xor_sync(0xFFFFFFFFu, v4[j], 1));
                v4[j] = fminf(v4[j], __shfl_xor_sync(0xFFFFFFFFu, v4[j], 2));
            }
            if ((lane & 3) == 0) {
                int row = lane >> 2;
                #pragma unroll
                for (int mi = 0; mi < 2; ++mi) {
                    int px0 = wm * 32 + mi * 16 + row;
                    min_sm[px0 * 2 + wn]       = v4[mi * 2 + 0];
                    min_sm[(px0 + 8) * 2 + wn] = v4[mi * 2 + 1];
                }
            }
            BAR_CONS();
            if (tid < 128) {
                float2 q = *(const float2*)(min_sm + tid * 2);
                float m = fminf(q.x, q.y);
                out[((size_t)n * OH + oh) * OW + ow0 + tid] = tanhf(tanhf(m));
            }
        } else {
            // ---- producers: stage plane oh+3 for the next row (5 tasks/warp) ----
            // slot (oh+3)&3 held plane oh-1, last read during row oh-1 (pre-barrier).
            if (oh + 1 < OH) {
                const int pw = wid - 8;
                #pragma unroll
                for (int j = 0; j < 5; ++j) {
                    int tk  = pw + 8 * j;     // 0..39
                    int oct = tk / 5;
                    int cg  = tk - oct * 5;
                    stage_task(x, n, oh + 3, ow0, oct, cg, lane, sb);
                }
            }
        }

        BAR_ALL();  // plane oh+3 visible; min_sm reads done; ring slot retire
    }
}

extern "C" void kernel_launch(void* const* d_in, const int* in_sizes, int n_in,
                              void* d_out, int out_size)
{
    const float* x    = (const float*)d_in[0];
    const float* wgt  = (const float*)d_in[1];
    const float* bias = (const float*)d_in[2];
    float* out        = (float*)d_out;

    cudaFuncSetAttribute(conv_min_tanh_ws,
                         cudaFuncAttributeMaxDynamicSharedMemorySize, SMEM_TOTAL);
    conv_min_tanh_ws<<<NSM, THREADS, SMEM_TOTAL>>>(x, wgt, bias, out);
}